// round 7
// baseline (speedup 1.0000x reference)
#include <cuda_runtime.h>

// y[o*16+k, n_out, m] = sum_{i<64, j<3} xs[i][m+j] * W[i, k, j]
// xs: W-rolled + zero-padded input row slab, row stride 60 floats.
//     xs[i][0] = xs[i][57..59] = 0;  xs[i][u] = x[c, n_src, w] with
//     u = w+2 (wrap to 1 when > 56)  -> patches[c,n_src,j,m] == xs[i][m+j].
// n_out = (n_src + 1) % 56 (output H-roll folded into the store).
//
// 1024 threads = 8 slices x 128. slice handles i in [slice*8, slice*8+8).
// Within a slice: k = t&15 (output channel), g = t>>4 in [0,8);
// g<7 computes outputs m = g*8 .. g*8+7 (7*8 = 56), g==7 idles in compute.
// Slices 1..7 spill 8 partials (stride 12: 16B-aligned, conflict-free);
// slice 0 reduces and stores via 2x float4.

__global__ __launch_bounds__(1024)
void shiftconv_kernel(const float* __restrict__ x,
                      const float* __restrict__ Wg,
                      float* __restrict__ y)
{
    __shared__ float xs[64 * 60];            // 15360 B
    __shared__ float Ws[64 * 48];            // 12288 B, layout [i][k*3+j]
    __shared__ float ps[7 * 112 * 12];       // 37632 B, partials

    const int n_src = blockIdx.x;            // 0..55
    const int o     = blockIdx.y;            // 0..1
    const int tid   = threadIdx.x;           // 0..1023

    // ---- stage W ----
    #pragma unroll
    for (int idx = tid; idx < 64 * 48; idx += 1024)
        Ws[idx] = Wg[idx];

    // ---- zero xs pad columns (u = 0, 57, 58, 59) ----
    if (tid < 64) {
        xs[tid * 60 + 0]  = 0.0f;
        xs[tid * 60 + 57] = 0.0f;
        xs[tid * 60 + 58] = 0.0f;
        xs[tid * 60 + 59] = 0.0f;
    }

    // ---- stage x: one float4 per thread (64 rows x 14 quads = 896) ----
    const float* xbase = x + (o * 64) * 3136 + n_src * 56;
    if (tid < 896) {
        const int i = tid / 14;
        const int q = tid - i * 14;
        const int w = q * 4;
        const float4 v = *(const float4*)(xbase + i * 3136 + w);
        float* row = &xs[i * 60];
        int u0 = w + 2; if (u0 > 56) u0 -= 56;
        int u1 = w + 3; if (u1 > 56) u1 -= 56;
        int u2 = w + 4; if (u2 > 56) u2 -= 56;
        int u3 = w + 5; if (u3 > 56) u3 -= 56;
        row[u0] = v.x; row[u1] = v.y; row[u2] = v.z; row[u3] = v.w;
    }
    __syncthreads();

    const int slice = tid >> 7;              // 0..7
    const int t128  = tid & 127;
    const int k     = t128 & 15;
    const int g     = t128 >> 4;             // 0..7 (7 == idle)
    const int m0    = g * 8;
    const int i0    = slice * 8;
    const bool live = (g < 7);

    float acc[8];
    #pragma unroll
    for (int t = 0; t < 8; t++) acc[t] = 0.0f;

    if (live) {
        #pragma unroll
        for (int ii = 0; ii < 8; ii++) {
            const int i = i0 + ii;
            const float* wrow = &Ws[i * 48 + k * 3];
            const float w0 = wrow[0];
            const float w1 = wrow[1];
            const float w2 = wrow[2];

            const float* xrow = &xs[i * 60 + m0];    // 16B aligned
            const float4 a = *(const float4*)(xrow);
            const float4 b = *(const float4*)(xrow + 4);
            const float2 c = *(const float2*)(xrow + 8);
            float xv[10] = {a.x, a.y, a.z, a.w, b.x, b.y, b.z, b.w, c.x, c.y};

            #pragma unroll
            for (int t = 0; t < 8; t++)
                acc[t] = fmaf(w2, xv[t + 2],
                         fmaf(w1, xv[t + 1],
                         fmaf(w0, xv[t], acc[t])));
        }
    }

    // ---- cross-slice reduction ----
    const int a_idx = g * 16 + k;            // 0..111 for live threads
    if (slice > 0 && live) {
        float* p = &ps[((slice - 1) * 112 + a_idx) * 12];
        *(float4*)(p)     = make_float4(acc[0], acc[1], acc[2], acc[3]);
        *(float4*)(p + 4) = make_float4(acc[4], acc[5], acc[6], acc[7]);
    }
    __syncthreads();

    if (slice == 0 && live) {
        #pragma unroll
        for (int s = 0; s < 7; s++) {
            const float* p = &ps[(s * 112 + a_idx) * 12];
            const float4 u = *(const float4*)(p);
            const float4 v = *(const float4*)(p + 4);
            acc[0] += u.x; acc[1] += u.y; acc[2] += u.z; acc[3] += u.w;
            acc[4] += v.x; acc[5] += v.y; acc[6] += v.z; acc[7] += v.w;
        }

        int n_out = n_src + 1;
        if (n_out == 56) n_out = 0;
        float* ybase = y + (o * 16 + k) * 3136 + n_out * 56 + m0;
        *(float4*)(ybase)     = make_float4(acc[0], acc[1], acc[2], acc[3]);
        *(float4*)(ybase + 4) = make_float4(acc[4], acc[5], acc[6], acc[7]);
    }
}

extern "C" void kernel_launch(void* const* d_in, const int* in_sizes, int n_in,
                              void* d_out, int out_size)
{
    const float* x  = (const float*)d_in[0];   // (1,128,56,56) = 401408
    const float* Wg = (const float*)d_in[1];   // (64,16,3)     = 3072
    float* y = (float*)d_out;                  // (1,32,56,56)  = 100352

    dim3 grid(56, 2);
    shiftconv_kernel<<<grid, 1024>>>(x, Wg, y);
}